// round 8
// baseline (speedup 1.0000x reference)
#include <cuda_runtime.h>
#include <math.h>

// ---------------------------------------------------------------------------
// HyperNet: CNN encoder -> FC -> VQ -> giant [4,16]x[16,T] streaming GEMM
// Inputs (metadata order):
//  0 rgb [4,3,224,224]
//  1..10 cw1,cb1,...,cw5,cb5
// 11 fc1_w [16,64]  12 fc1_b [16]
// 13 fc2_w [16,16]  14 fc2_b [16]
// 15 emb  [4,16]
// 16 W_all [16, T]   (T = in_sizes[16]/16 = 35,968,706)
// Output: flat [4,T] row-major, then loss scalar (if out_size == 4T+1)
// ---------------------------------------------------------------------------

// Scratch (device globals — no allocation allowed)
__device__ float g_c1[4 * 4 * 112 * 112];
__device__ float g_c2[4 * 8 * 56 * 56];
__device__ float g_c3[4 * 16 * 28 * 28];
__device__ float g_c4[4 * 32 * 14 * 14];
__device__ float g_c5[4 * 64 * 7 * 7];
__device__ float g_qst[64];   // q_st == emb[idx[b]]  [4][16]
__device__ float g_loss;

// ---------------------------------------------------------------------------
// Generic strided conv (k=4, s=2, p=1), one thread per output element.
// ---------------------------------------------------------------------------
template <int CIN, int COUT, int IN, int OUT, bool RELU>
__global__ void conv_k(const float* __restrict__ in, const float* __restrict__ w,
                       const float* __restrict__ bias, float* __restrict__ out) {
    int idx = blockIdx.x * blockDim.x + threadIdx.x;
    const int total = 4 * COUT * OUT * OUT;
    if (idx >= total) return;
    int x = idx % OUT;
    int y = (idx / OUT) % OUT;
    int o = (idx / (OUT * OUT)) % COUT;
    int n = idx / (OUT * OUT * COUT);

    float acc = bias[o];
    const float* wp = w + o * CIN * 16;          // [CIN][4][4]
    const float* ip = in + n * CIN * IN * IN;    // [CIN][IN][IN]

#pragma unroll
    for (int ky = 0; ky < 4; ky++) {
        int iy = 2 * y - 1 + ky;
        if ((unsigned)iy < (unsigned)IN) {
#pragma unroll
            for (int kx = 0; kx < 4; kx++) {
                int ix = 2 * x - 1 + kx;
                if ((unsigned)ix < (unsigned)IN) {
                    for (int i = 0; i < CIN; i++) {
                        acc = fmaf(ip[(i * IN + iy) * IN + ix],
                                   wp[(i * 4 + ky) * 4 + kx], acc);
                    }
                }
            }
        }
    }
    if (RELU) acc = acc >= 0.f ? acc : 0.01f * acc;
    out[idx] = acc;
}

// ---------------------------------------------------------------------------
// Head: avgpool(7x7) -> fc1+lrelu -> fc2 -> VQ argmin -> q_st + loss
// Single block, 256 threads.
// ---------------------------------------------------------------------------
__global__ void head_k(const float* __restrict__ fc1w, const float* __restrict__ fc1b,
                       const float* __restrict__ fc2w, const float* __restrict__ fc2b,
                       const float* __restrict__ emb) {
    __shared__ float pooled[4][64];
    __shared__ float h[4][16];
    __shared__ float e[4][16];
    __shared__ int idx_s[4];
    int t = threadIdx.x;

    // avg-pool conv5 [4,64,7,7]
    {
        int n = t >> 6, c = t & 63;
        const float* p = g_c5 + (n * 64 + c) * 49;
        float s = 0.f;
#pragma unroll
        for (int i = 0; i < 49; i++) s += p[i];
        pooled[n][c] = s * (1.f / 49.f);
    }
    __syncthreads();

    // fc1 [16,64] + lrelu
    if (t < 64) {
        int n = t >> 4, j = t & 15;
        float s = fc1b[j];
        for (int c = 0; c < 64; c++) s = fmaf(pooled[n][c], fc1w[j * 64 + c], s);
        h[n][j] = s >= 0.f ? s : 0.01f * s;
    }
    __syncthreads();

    // fc2 [16,16]
    if (t < 64) {
        int n = t >> 4, j = t & 15;
        float s = fc2b[j];
        for (int c = 0; c < 16; c++) s = fmaf(h[n][c], fc2w[j * 16 + c], s);
        e[n][j] = s;
    }
    __syncthreads();

    // VQ: d = |e|^2 + |emb_j|^2 - 2 e.emb_j, argmin (first-min tie-break)
    if (t < 4) {
        int n = t;
        float ee = 0.f;
        for (int k = 0; k < 16; k++) ee += e[n][k] * e[n][k];
        float best = INFINITY;
        int bi = 0;
        for (int j = 0; j < 4; j++) {
            float em2 = 0.f, dot = 0.f;
            for (int k = 0; k < 16; k++) {
                float ev = emb[j * 16 + k];
                em2 += ev * ev;
                dot += e[n][k] * ev;
            }
            float d = ee + em2 - 2.f * dot;
            if (d < best) { best = d; bi = j; }
        }
        idx_s[n] = bi;
    }
    __syncthreads();

    // q_st (numerically == emb[idx])
    if (t < 64) {
        int n = t >> 4, k = t & 15;
        g_qst[t] = emb[idx_s[n] * 16 + k];
    }
    __syncthreads();

    // loss = 1.25 * mean((q-e)^2)
    if (t == 0) {
        float s = 0.f;
        for (int n = 0; n < 4; n++)
            for (int k = 0; k < 16; k++) {
                float d = emb[idx_s[n] * 16 + k] - e[n][k];
                s += d * d;
            }
        g_loss = 1.25f * (s * (1.f / 64.f));
    }
}

// ---------------------------------------------------------------------------
// Streaming GEMM: out[b,t] = sum_k q[b][k] * W[k,t]
// float2 vectorized (T even; row starts are 8B- but not 16B-aligned).
// Streaming cache hints: the 2.9 GB working set is 23x L2 — evict-first.
// ---------------------------------------------------------------------------
__global__ __launch_bounds__(256, 2)
void hyper_gemm(const float* __restrict__ W, float* __restrict__ out,
                int T2 /* = T/2 */, int write_loss) {
    // hoist q into registers (broadcast, L1-resident)
    float q[64];
#pragma unroll
    for (int i = 0; i < 64; i++) q[i] = g_qst[i];

    const float2* __restrict__ W2 = (const float2*)W;
    float2* out2 = (float2*)out;
    const long long T2l = (long long)T2;
    long long stride = (long long)gridDim.x * blockDim.x;

    for (long long t = (long long)blockIdx.x * blockDim.x + threadIdx.x;
         t < T2l; t += stride) {
        float2 wv[16];
#pragma unroll
        for (int k = 0; k < 16; k++) wv[k] = __ldcs(&W2[(long long)k * T2l + t]);

        float2 a0 = {0.f, 0.f}, a1 = {0.f, 0.f}, a2 = {0.f, 0.f}, a3 = {0.f, 0.f};
#pragma unroll
        for (int k = 0; k < 16; k++) {
            float wx = wv[k].x, wy = wv[k].y;
            a0.x = fmaf(q[k],      wx, a0.x);  a0.y = fmaf(q[k],      wy, a0.y);
            a1.x = fmaf(q[16 + k], wx, a1.x);  a1.y = fmaf(q[16 + k], wy, a1.y);
            a2.x = fmaf(q[32 + k], wx, a2.x);  a2.y = fmaf(q[32 + k], wy, a2.y);
            a3.x = fmaf(q[48 + k], wx, a3.x);  a3.y = fmaf(q[48 + k], wy, a3.y);
        }
        __stcs(&out2[t],           a0);
        __stcs(&out2[T2l + t],     a1);
        __stcs(&out2[2 * T2l + t], a2);
        __stcs(&out2[3 * T2l + t], a3);
    }

    if (write_loss && blockIdx.x == 0 && threadIdx.x == 0)
        out[(long long)4 * 2 * T2l] = g_loss;
}

// ---------------------------------------------------------------------------
extern "C" void kernel_launch(void* const* d_in, const int* in_sizes, int n_in,
                              void* d_out, int out_size) {
    const float* rgb  = (const float*)d_in[0];
    const float* cw1  = (const float*)d_in[1];
    const float* cb1  = (const float*)d_in[2];
    const float* cw2  = (const float*)d_in[3];
    const float* cb2  = (const float*)d_in[4];
    const float* cw3  = (const float*)d_in[5];
    const float* cb3  = (const float*)d_in[6];
    const float* cw4  = (const float*)d_in[7];
    const float* cb4  = (const float*)d_in[8];
    const float* cw5  = (const float*)d_in[9];
    const float* cb5  = (const float*)d_in[10];
    const float* fc1w = (const float*)d_in[11];
    const float* fc1b = (const float*)d_in[12];
    const float* fc2w = (const float*)d_in[13];
    const float* fc2b = (const float*)d_in[14];
    const float* emb  = (const float*)d_in[15];
    const float* Wall = (const float*)d_in[16];
    float* out = (float*)d_out;

    long long T = (long long)in_sizes[16] / 16;   // 35,968,706
    int T2 = (int)(T / 2);
    int write_loss = ((long long)out_size > 4 * T) ? 1 : 0;

    float *c1, *c2, *c3, *c4, *c5;
    cudaGetSymbolAddress((void**)&c1, g_c1);
    cudaGetSymbolAddress((void**)&c2, g_c2);
    cudaGetSymbolAddress((void**)&c3, g_c3);
    cudaGetSymbolAddress((void**)&c4, g_c4);
    cudaGetSymbolAddress((void**)&c5, g_c5);

    conv_k<3, 4, 224, 112, true ><<<(4 * 4 * 112 * 112 + 255) / 256, 256>>>(rgb, cw1, cb1, c1);
    conv_k<4, 8, 112, 56,  true ><<<(4 * 8 * 56 * 56 + 255) / 256, 256>>>(c1, cw2, cb2, c2);
    conv_k<8, 16, 56, 28,  true ><<<(4 * 16 * 28 * 28 + 255) / 256, 256>>>(c2, cw3, cb3, c3);
    conv_k<16, 32, 28, 14, true ><<<(4 * 32 * 14 * 14 + 255) / 256, 256>>>(c3, cw4, cb4, c4);
    conv_k<32, 64, 14, 7,  false><<<(4 * 64 * 7 * 7 + 255) / 256, 256>>>(c4, cw5, cb5, c5);

    head_k<<<1, 256>>>(fc1w, fc1b, fc2w, fc2b, emb);

    // 148+ SMs * 16 blocks, 256 thr: ~30 float2 per thread, grid-stride
    hyper_gemm<<<2368, 256>>>(Wall, out, T2, write_loss);
}

// round 9
// speedup vs baseline: 1.0031x; 1.0031x over previous
#include <cuda_runtime.h>
#include <math.h>

// ---------------------------------------------------------------------------
// HyperNet: CNN encoder -> FC -> VQ -> giant [4,16]x[16,T] streaming GEMM
// Inputs (metadata order):
//  0 rgb [4,3,224,224]
//  1..10 cw1,cb1,...,cw5,cb5
// 11 fc1_w [16,64]  12 fc1_b [16]
// 13 fc2_w [16,16]  14 fc2_b [16]
// 15 emb  [4,16]
// 16 W_all [16, T]   (T = in_sizes[16]/16 = 35,968,706)
// Output: flat [4,T] row-major, then loss scalar (if out_size == 4T+1)
// ---------------------------------------------------------------------------

// Scratch (device globals — no allocation allowed)
__device__ float g_c1[4 * 4 * 112 * 112];
__device__ float g_c2[4 * 8 * 56 * 56];
__device__ float g_c3[4 * 16 * 28 * 28];
__device__ float g_c4[4 * 32 * 14 * 14];
__device__ float g_c5[4 * 64 * 7 * 7];
__device__ float g_qst[64];   // q_st == emb[idx[b]]  [4][16]
__device__ float g_loss;

// ---------------------------------------------------------------------------
// Plain strided conv (k=4, s=2, p=1), one thread per output element.
// Used for conv1 (CIN=3) and conv2 (CIN=4) where parallelism is already ample.
// ---------------------------------------------------------------------------
template <int CIN, int COUT, int IN, int OUT, bool RELU>
__global__ void conv_k(const float* __restrict__ in, const float* __restrict__ w,
                       const float* __restrict__ bias, float* __restrict__ out) {
    int idx = blockIdx.x * blockDim.x + threadIdx.x;
    const int total = 4 * COUT * OUT * OUT;
    if (idx >= total) return;
    int x = idx % OUT;
    int y = (idx / OUT) % OUT;
    int o = (idx / (OUT * OUT)) % COUT;
    int n = idx / (OUT * OUT * COUT);

    float acc = bias[o];
    const float* wp = w + o * CIN * 16;          // [CIN][4][4]
    const float* ip = in + n * CIN * IN * IN;    // [CIN][IN][IN]

#pragma unroll
    for (int ky = 0; ky < 4; ky++) {
        int iy = 2 * y - 1 + ky;
        if ((unsigned)iy < (unsigned)IN) {
#pragma unroll
            for (int kx = 0; kx < 4; kx++) {
                int ix = 2 * x - 1 + kx;
                if ((unsigned)ix < (unsigned)IN) {
#pragma unroll
                    for (int i = 0; i < CIN; i++) {
                        acc = fmaf(ip[(i * IN + iy) * IN + ix],
                                   wp[(i * 4 + ky) * 4 + kx], acc);
                    }
                }
            }
        }
    }
    if (RELU) acc = acc >= 0.f ? acc : 0.01f * acc;
    out[idx] = acc;
}

// ---------------------------------------------------------------------------
// Split-K conv: SPLIT threads per output element, each covering CIN/SPLIT
// input channels; reduce via warp shuffle. Cuts the serial FMA chain SPLIT×
// and multiplies thread count SPLIT× (these deep convs are latency-bound).
// SPLIT must divide 32 (lane groups stay inside a warp).
// ---------------------------------------------------------------------------
template <int CIN, int COUT, int IN, int OUT, int SPLIT, bool RELU>
__global__ void conv_split_k(const float* __restrict__ in, const float* __restrict__ w,
                             const float* __restrict__ bias, float* __restrict__ out) {
    int g = blockIdx.x * blockDim.x + threadIdx.x;
    const int total = 4 * COUT * OUT * OUT * SPLIT;
    if (g >= total) return;
    int part = g % SPLIT;
    int idx = g / SPLIT;

    int x = idx % OUT;
    int y = (idx / OUT) % OUT;
    int o = (idx / (OUT * OUT)) % COUT;
    int n = idx / (OUT * OUT * COUT);

    constexpr int CPT = CIN / SPLIT;
    int c0 = part * CPT;

    float acc = 0.f;
    const float* wp = w + (o * CIN + c0) * 16;       // [CPT][4][4]
    const float* ip = in + (n * CIN + c0) * IN * IN; // [CPT][IN][IN]

#pragma unroll
    for (int ky = 0; ky < 4; ky++) {
        int iy = 2 * y - 1 + ky;
        if ((unsigned)iy < (unsigned)IN) {
#pragma unroll
            for (int kx = 0; kx < 4; kx++) {
                int ix = 2 * x - 1 + kx;
                if ((unsigned)ix < (unsigned)IN) {
#pragma unroll
                    for (int i = 0; i < CPT; i++) {
                        acc = fmaf(ip[(i * IN + iy) * IN + ix],
                                   wp[(i * 4 + ky) * 4 + kx], acc);
                    }
                }
            }
        }
    }

    // reduce across the SPLIT-lane group (contiguous lanes)
#pragma unroll
    for (int off = SPLIT >> 1; off > 0; off >>= 1)
        acc += __shfl_xor_sync(0xffffffffu, acc, off);

    if (part == 0) {
        acc += bias[o];
        if (RELU) acc = acc >= 0.f ? acc : 0.01f * acc;
        out[idx] = acc;
    }
}

// ---------------------------------------------------------------------------
// Head: avgpool(7x7) -> fc1+lrelu -> fc2 -> VQ argmin -> q_st + loss
// Single block, 256 threads.
// ---------------------------------------------------------------------------
__global__ void head_k(const float* __restrict__ fc1w, const float* __restrict__ fc1b,
                       const float* __restrict__ fc2w, const float* __restrict__ fc2b,
                       const float* __restrict__ emb) {
    __shared__ float pooled[4][64];
    __shared__ float h[4][16];
    __shared__ float e[4][16];
    __shared__ int idx_s[4];
    int t = threadIdx.x;

    // avg-pool conv5 [4,64,7,7]
    {
        int n = t >> 6, c = t & 63;
        const float* p = g_c5 + (n * 64 + c) * 49;
        float s = 0.f;
#pragma unroll
        for (int i = 0; i < 49; i++) s += p[i];
        pooled[n][c] = s * (1.f / 49.f);
    }
    __syncthreads();

    // fc1 [16,64] + lrelu
    if (t < 64) {
        int n = t >> 4, j = t & 15;
        float s = fc1b[j];
        for (int c = 0; c < 64; c++) s = fmaf(pooled[n][c], fc1w[j * 64 + c], s);
        h[n][j] = s >= 0.f ? s : 0.01f * s;
    }
    __syncthreads();

    // fc2 [16,16]
    if (t < 64) {
        int n = t >> 4, j = t & 15;
        float s = fc2b[j];
        for (int c = 0; c < 16; c++) s = fmaf(h[n][c], fc2w[j * 16 + c], s);
        e[n][j] = s;
    }
    __syncthreads();

    // VQ: d = |e|^2 + |emb_j|^2 - 2 e.emb_j, argmin (first-min tie-break)
    if (t < 4) {
        int n = t;
        float ee = 0.f;
        for (int k = 0; k < 16; k++) ee += e[n][k] * e[n][k];
        float best = INFINITY;
        int bi = 0;
        for (int j = 0; j < 4; j++) {
            float em2 = 0.f, dot = 0.f;
            for (int k = 0; k < 16; k++) {
                float ev = emb[j * 16 + k];
                em2 += ev * ev;
                dot += e[n][k] * ev;
            }
            float d = ee + em2 - 2.f * dot;
            if (d < best) { best = d; bi = j; }
        }
        idx_s[n] = bi;
    }
    __syncthreads();

    // q_st (numerically == emb[idx])
    if (t < 64) {
        int n = t >> 4, k = t & 15;
        g_qst[t] = emb[idx_s[n] * 16 + k];
    }
    __syncthreads();

    // loss = 1.25 * mean((q-e)^2)
    if (t == 0) {
        float s = 0.f;
        for (int n = 0; n < 4; n++)
            for (int k = 0; k < 16; k++) {
                float d = emb[idx_s[n] * 16 + k] - e[n][k];
                s += d * d;
            }
        g_loss = 1.25f * (s * (1.f / 64.f));
    }
}

// ---------------------------------------------------------------------------
// Streaming GEMM: out[b,t] = sum_k q[b][k] * W[k,t]
// float2 vectorized (T even; odd-row starts are only 8B-aligned -> no float4).
// Persistent grid (2 CTAs/SM * 152 SMs): no wave transitions, q-load amortized
// over ~237 iterations/thread. Evict-first cache hints (2.9 GB >> L2).
// ---------------------------------------------------------------------------
__global__ __launch_bounds__(256, 2)
void hyper_gemm(const float* __restrict__ W, float* __restrict__ out,
                int T2 /* = T/2 */, int write_loss) {
    // hoist q into registers (broadcast, L1-resident)
    float q[64];
#pragma unroll
    for (int i = 0; i < 64; i++) q[i] = g_qst[i];

    const float2* __restrict__ W2 = (const float2*)W;
    float2* out2 = (float2*)out;
    const long long T2l = (long long)T2;
    const long long stride = (long long)gridDim.x * blockDim.x;

    for (long long t = (long long)blockIdx.x * blockDim.x + threadIdx.x;
         t < T2l; t += stride) {
        float2 wv[16];
#pragma unroll
        for (int k = 0; k < 16; k++) wv[k] = __ldcs(&W2[(long long)k * T2l + t]);

        float2 a0 = {0.f, 0.f}, a1 = {0.f, 0.f}, a2 = {0.f, 0.f}, a3 = {0.f, 0.f};
#pragma unroll
        for (int k = 0; k < 16; k++) {
            float wx = wv[k].x, wy = wv[k].y;
            a0.x = fmaf(q[k],      wx, a0.x);  a0.y = fmaf(q[k],      wy, a0.y);
            a1.x = fmaf(q[16 + k], wx, a1.x);  a1.y = fmaf(q[16 + k], wy, a1.y);
            a2.x = fmaf(q[32 + k], wx, a2.x);  a2.y = fmaf(q[32 + k], wy, a2.y);
            a3.x = fmaf(q[48 + k], wx, a3.x);  a3.y = fmaf(q[48 + k], wy, a3.y);
        }
        __stcs(&out2[t],           a0);
        __stcs(&out2[T2l + t],     a1);
        __stcs(&out2[2 * T2l + t], a2);
        __stcs(&out2[3 * T2l + t], a3);
    }

    if (write_loss && blockIdx.x == 0 && threadIdx.x == 0)
        out[(long long)4 * 2 * T2l] = g_loss;
}

// ---------------------------------------------------------------------------
extern "C" void kernel_launch(void* const* d_in, const int* in_sizes, int n_in,
                              void* d_out, int out_size) {
    const float* rgb  = (const float*)d_in[0];
    const float* cw1  = (const float*)d_in[1];
    const float* cb1  = (const float*)d_in[2];
    const float* cw2  = (const float*)d_in[3];
    const float* cb2  = (const float*)d_in[4];
    const float* cw3  = (const float*)d_in[5];
    const float* cb3  = (const float*)d_in[6];
    const float* cw4  = (const float*)d_in[7];
    const float* cb4  = (const float*)d_in[8];
    const float* cw5  = (const float*)d_in[9];
    const float* cb5  = (const float*)d_in[10];
    const float* fc1w = (const float*)d_in[11];
    const float* fc1b = (const float*)d_in[12];
    const float* fc2w = (const float*)d_in[13];
    const float* fc2b = (const float*)d_in[14];
    const float* emb  = (const float*)d_in[15];
    const float* Wall = (const float*)d_in[16];
    float* out = (float*)d_out;

    long long T = (long long)in_sizes[16] / 16;   // 35,968,706
    int T2 = (int)(T / 2);
    int write_loss = ((long long)out_size > 4 * T) ? 1 : 0;

    float *c1, *c2, *c3, *c4, *c5;
    cudaGetSymbolAddress((void**)&c1, g_c1);
    cudaGetSymbolAddress((void**)&c2, g_c2);
    cudaGetSymbolAddress((void**)&c3, g_c3);
    cudaGetSymbolAddress((void**)&c4, g_c4);
    cudaGetSymbolAddress((void**)&c5, g_c5);

    // conv1/conv2: ample parallelism, keep one-thread-per-output
    conv_k<3, 4, 224, 112, true ><<<(4 * 4 * 112 * 112 + 255) / 256, 256>>>(rgb, cw1, cb1, c1);
    conv_k<4, 8, 112, 56,  true ><<<(4 * 8 * 56 * 56 + 255) / 256, 256>>>(c1, cw2, cb2, c2);
    // conv3/4/5: latency-bound deep channels -> split-K with shuffle reduce
    conv_split_k<8, 16, 56, 28,  2, true ><<<(4 * 16 * 28 * 28 * 2 + 255) / 256, 256>>>(c2, cw3, cb3, c3);
    conv_split_k<16, 32, 28, 14, 4, true ><<<(4 * 32 * 14 * 14 * 4 + 255) / 256, 256>>>(c3, cw4, cb4, c4);
    conv_split_k<32, 64, 14, 7,  8, false><<<(4 * 64 * 7 * 7 * 8 + 255) / 256, 256>>>(c4, cw5, cb5, c5);

    head_k<<<1, 256>>>(fc1w, fc1b, fc2w, fc2b, emb);

    // persistent grid: 2 CTAs/SM on 152 SMs, grid-stride over T2
    hyper_gemm<<<304, 256>>>(Wall, out, T2, write_loss);
}